// round 5
// baseline (speedup 1.0000x reference)
#include <cuda_runtime.h>
#include <cstdint>
#include <cstddef>

#define N      16384
#define C      128
#define KNN    9
#define KCAND  16
#define COUT   256
#define BR     64      // rows per fused block
#define JT     256     // j-tile width
#define NJT    (N / JT)

// Scratch (static __device__ arrays per harness rules; no cudaMalloc anywhere)
__device__ float g_sq[N];
__device__ int   g_cand[N * KCAND];
__device__ int   g_nbr[N * KNN];
__device__ float g_x2[(size_t)N * C];

// dynamic smem layout (floats): As[128][68] | Bs[32][260] | lv[64][16] | li[64][16] | worst[64]
#define AS_PITCH 68
#define BS_PITCH 260
#define SM_AS    0
#define SM_BS    (128 * AS_PITCH)
#define SM_LV    (SM_BS + 32 * BS_PITCH)
#define SM_LI    (SM_LV + BR * KCAND)
#define SM_W     (SM_LI + BR * KCAND)
#define SM_FLOATS (SM_W + BR)

// ---------------------------------------------------------------------------
// 1) squared norms -- replicate an LLVM/XLA vectorized reduce:
//    VF=4, IC=2 -> 8 stride-8 fmaf partial sums, lane-wise combine of the two
//    interleaved vectors, then horizontal tree (l0+l2)+(l1+l3).
// ---------------------------------------------------------------------------
__global__ void sqnorm_kernel(const float* __restrict__ x) {
    int i = blockIdx.x * blockDim.x + threadIdx.x;
    if (i >= N) return;
    const float* r = x + (size_t)i * C;
    float p[8];
#pragma unroll
    for (int l = 0; l < 8; l++) p[l] = 0.f;
#pragma unroll
    for (int k = 0; k < C / 8; k++)
#pragma unroll
        for (int l = 0; l < 8; l++) {
            float v = r[8 * k + l];
            p[l] = fmaf(v, v, p[l]);
        }
    float v0 = p[0] + p[4];
    float v1 = p[1] + p[5];
    float v2 = p[2] + p[6];
    float v3 = p[3] + p[7];
    g_sq[i] = (v0 + v2) + (v1 + v3);
}

// ---------------------------------------------------------------------------
// 2) FUSED distance GEMM + per-row top-16 nomination.
//    Block owns 64 rows (A resident in smem), sweeps all N cols in tiles of
//    256. FMA chain ordering identical to previous rounds (k ascending,
//    single chain) -> bit-identical fp32 distances -> identical candidates.
//    Each warp owns 8 rows; top-16 lists live in shared, warp-private.
// ---------------------------------------------------------------------------
__global__ __launch_bounds__(256, 2)
void fused_dist_topk(const float* __restrict__ x) {
    extern __shared__ float sm[];
    float* As  = sm + SM_AS;
    float* Bs  = sm + SM_BS;
    float* lv  = sm + SM_LV;
    int*   li  = (int*)(sm + SM_LI);
    float* swt = sm + SM_W;

    const int tid  = threadIdx.x;
    const int lane = tid & 31;
    const int r0   = blockIdx.x * BR;
    const int tm   = (tid >> 5) << 3;   // warp-uniform: rows tm..tm+7
    const int tn   = lane << 3;         // cols tn..tn+7 within j-tile
    const float INFV = __int_as_float(0x7f800000);

    // init candidate lists
    for (int idx = tid; idx < BR * KCAND; idx += 256) { lv[idx] = INFV; li[idx] = 0x7fffffff; }
    if (tid < BR) swt[tid] = INFV;

    // load A tile (64 rows x 128 ch) transposed into As[k][m]
#pragma unroll
    for (int it = 0; it < 8; it++) {
        int idx = tid + it * 256;        // 0..2047
        int row = idx >> 5;              // 0..63
        int c4  = (idx & 31) << 2;       // 0..124
        float4 a = *reinterpret_cast<const float4*>(&x[(size_t)(r0 + row) * C + c4]);
        As[(c4 + 0) * AS_PITCH + row] = a.x;
        As[(c4 + 1) * AS_PITCH + row] = a.y;
        As[(c4 + 2) * AS_PITCH + row] = a.z;
        As[(c4 + 3) * AS_PITCH + row] = a.w;
    }
    __syncthreads();

    float sqi[8];
#pragma unroll
    for (int a = 0; a < 8; a++) sqi[a] = g_sq[r0 + tm + a];

    for (int jt = 0; jt < NJT; jt++) {
        const int j0 = jt * JT;
        float acc[8][8];
#pragma unroll
        for (int a = 0; a < 8; a++)
#pragma unroll
            for (int bq = 0; bq < 8; bq++) acc[a][bq] = 0.f;

        for (int kc = 0; kc < 4; kc++) {
            __syncthreads();   // Bs free from previous chunk
#pragma unroll
            for (int v = 0; v < 8; v++) {
                int idx = tid + v * 256;     // 0..2047
                int r   = idx >> 3;          // 0..255
                int c4  = (idx & 7) << 2;    // 0..28
                float4 bb = *reinterpret_cast<const float4*>(
                    &x[(size_t)(j0 + r) * C + kc * 32 + c4]);
                Bs[(c4 + 0) * BS_PITCH + r] = bb.x;
                Bs[(c4 + 1) * BS_PITCH + r] = bb.y;
                Bs[(c4 + 2) * BS_PITCH + r] = bb.z;
                Bs[(c4 + 3) * BS_PITCH + r] = bb.w;
            }
            __syncthreads();
#pragma unroll
            for (int k = 0; k < 32; k++) {
                float av[8], bv[8];
                *reinterpret_cast<float4*>(&av[0]) =
                    *reinterpret_cast<const float4*>(&As[(kc * 32 + k) * AS_PITCH + tm]);
                *reinterpret_cast<float4*>(&av[4]) =
                    *reinterpret_cast<const float4*>(&As[(kc * 32 + k) * AS_PITCH + tm + 4]);
                *reinterpret_cast<float4*>(&bv[0]) =
                    *reinterpret_cast<const float4*>(&Bs[k * BS_PITCH + tn]);
                *reinterpret_cast<float4*>(&bv[4]) =
                    *reinterpret_cast<const float4*>(&Bs[k * BS_PITCH + tn + 4]);
#pragma unroll
                for (int a = 0; a < 8; a++)
#pragma unroll
                    for (int bq = 0; bq < 8; bq++)
                        acc[a][bq] = fmaf(av[a], bv[bq], acc[a][bq]);
            }
        }

        // ---- selection: warp-private rows, ballot-serialized inserts ----
#pragma unroll
        for (int a = 0; a < 8; a++) {
            const int row = tm + a;
            const float w = swt[row];
            float dvv[8];
            bool any = false;
#pragma unroll
            for (int bq = 0; bq < 8; bq++) {
                int j = j0 + tn + bq;
                float dv = (sqi[a] + g_sq[j]) - 2.f * acc[a][bq];
                if (r0 + row == j) dv = INFV;
                dvv[bq] = dv;
                any |= (dv < w);
            }
            unsigned bal = __ballot_sync(0xffffffffu, any);
            while (bal) {
                int leader = __ffs(bal) - 1;
                bal &= bal - 1;
                if (lane == leader) {
#pragma unroll
                    for (int bq = 0; bq < 8; bq++) {
                        float dv = dvv[bq];
                        if (dv < swt[row]) {
                            int jj = j0 + tn + bq;
                            int pos = 0;
                            while (pos < KCAND && lv[row * KCAND + pos] <= dv) pos++;
                            for (int q = KCAND - 1; q > pos; q--) {
                                lv[row * KCAND + q] = lv[row * KCAND + q - 1];
                                li[row * KCAND + q] = li[row * KCAND + q - 1];
                            }
                            lv[row * KCAND + pos] = dv;
                            li[row * KCAND + pos] = jj;
                            swt[row] = lv[row * KCAND + KCAND - 1];
                        }
                    }
                }
                __syncwarp();
            }
        }
    }

    __syncwarp();
    // write candidates (rows warp-private; sorted by (val, idx) ascending)
    for (int idx = lane; idx < 8 * KCAND; idx += 32) {
        int rr = tm + idx / KCAND;
        int t  = idx % KCAND;
        g_cand[(size_t)(r0 + rr) * KCAND + t] = li[rr * KCAND + t];
    }
}

// ---------------------------------------------------------------------------
// 3) authoritative fp32 re-rank of the 16 candidates, replicating the
//    reference arithmetic: dot = single ascending-k fp32 FMA chain,
//    d = (sq_i + sq_j) - 2*dot, tie-break by lower index.
//    One warp per row; lane t owns candidate t.
// ---------------------------------------------------------------------------
__global__ __launch_bounds__(128)
void refine_kernel(const float* __restrict__ x) {
    __shared__ float sxi[4][128];
    const int warp = threadIdx.x >> 5;
    const int lane = threadIdx.x & 31;
    const int row  = blockIdx.x * 4 + warp;

#pragma unroll
    for (int q = 0; q < 4; q++)
        sxi[warp][lane + 32 * q] = x[(size_t)row * C + lane + 32 * q];
    __syncwarp();

    float d = __int_as_float(0x7f800000);
    int   j = 0x7fffffff;
    if (lane < KCAND) {
        j = g_cand[row * KCAND + lane];
        const float* xj = x + (size_t)j * C;
        float acc = 0.f;
#pragma unroll
        for (int k = 0; k < C; k += 4) {
            float4 v = *reinterpret_cast<const float4*>(xj + k);
            acc = fmaf(sxi[warp][k + 0], v.x, acc);
            acc = fmaf(sxi[warp][k + 1], v.y, acc);
            acc = fmaf(sxi[warp][k + 2], v.z, acc);
            acc = fmaf(sxi[warp][k + 3], v.w, acc);
        }
        d = (g_sq[row] + g_sq[j]) - 2.f * acc;
    }

    // lane 0 gathers, sorts by (d, index) with a static bubble network
    float dv[KCAND];
    int   di[KCAND];
#pragma unroll
    for (int t = 0; t < KCAND; t++) {
        dv[t] = __shfl_sync(0xffffffffu, d, t);
        di[t] = __shfl_sync(0xffffffffu, j, t);
    }
    if (lane == 0) {
#pragma unroll
        for (int a = 0; a < KCAND - 1; a++)
#pragma unroll
            for (int bq = 0; bq < KCAND - 1; bq++) {
                bool sw = dv[bq] > dv[bq + 1] ||
                          (dv[bq] == dv[bq + 1] && di[bq] > di[bq + 1]);
                float tv = sw ? dv[bq + 1] : dv[bq];
                dv[bq + 1] = sw ? dv[bq] : dv[bq + 1]; dv[bq] = tv;
                int ti = sw ? di[bq + 1] : di[bq];
                di[bq + 1] = sw ? di[bq] : di[bq + 1]; di[bq] = ti;
            }
#pragma unroll
        for (int t = 0; t < KNN; t++) g_nbr[row * KNN + t] = di[t];
    }
}

// ---------------------------------------------------------------------------
// 4) x2 = x + rel_pos_table[rel], rel[i] = i/128 - i%128 + 127
// ---------------------------------------------------------------------------
__global__ void relpos_kernel(const float* __restrict__ x, const float* __restrict__ tab) {
    int idx = blockIdx.x * blockDim.x + threadIdx.x;   // over N*C
    int i   = idx >> 7;
    int c   = idx & 127;
    int rel = (i >> 7) - (i & 127) + (C - 1);
    g_x2[idx] = x[idx] + tab[(size_t)rel * C + c];
}

// ---------------------------------------------------------------------------
// 5) gather + max-relative + concat-GEMM (+ bias at the end). 16 rows/block.
// ---------------------------------------------------------------------------
__global__ __launch_bounds__(256)
void final_kernel(const float* __restrict__ W, const float* __restrict__ b,
                  float* __restrict__ out) {
    __shared__ float feat[16][260];   // [x2 | m], padded row
    const int r0   = blockIdx.x * 16;
    const int tid  = threadIdx.x;
    const int half = tid >> 7;
    const int c    = tid & 127;
    const float NEGINF = __int_as_float(0xff800000);

#pragma unroll
    for (int rr = 0; rr < 16; rr += 2) {
        int r = rr + half;
        int i = r0 + r;
        float xi = g_x2[(size_t)i * C + c];
        float m  = NEGINF;
#pragma unroll
        for (int k = 0; k < KNN; k++) {
            int j = g_nbr[i * KNN + k];
            m = fmaxf(m, g_x2[(size_t)j * C + c] - xi);
        }
        feat[r][c]     = xi;
        feat[r][C + c] = m;
    }
    __syncthreads();

    const int o = tid;   // output column 0..255
    float acc[16];
#pragma unroll
    for (int r = 0; r < 16; r++) acc[r] = 0.f;

    for (int f = 0; f < 2 * C; f += 4) {
        float w0 = W[(size_t)(f + 0) * COUT + o];
        float w1 = W[(size_t)(f + 1) * COUT + o];
        float w2 = W[(size_t)(f + 2) * COUT + o];
        float w3 = W[(size_t)(f + 3) * COUT + o];
#pragma unroll
        for (int r = 0; r < 16; r++) {
            float4 fv = *reinterpret_cast<const float4*>(&feat[r][f]);
            acc[r] = fmaf(fv.x, w0, acc[r]);
            acc[r] = fmaf(fv.y, w1, acc[r]);
            acc[r] = fmaf(fv.z, w2, acc[r]);
            acc[r] = fmaf(fv.w, w3, acc[r]);
        }
    }
    float bias = b[o];
#pragma unroll
    for (int r = 0; r < 16; r++)
        out[(size_t)(r0 + r) * COUT + o] = acc[r] + bias;
}

// ---------------------------------------------------------------------------
extern "C" void kernel_launch(void* const* d_in, const int* in_sizes, int n_in,
                              void* d_out, int out_size) {
    const float* x   = (const float*)d_in[0];
    const float* tab = (const float*)d_in[1];
    const float* W   = (const float*)d_in[2];
    const float* b   = (const float*)d_in[3];
    float* out = (float*)d_out;
    (void)in_sizes; (void)n_in; (void)out_size;

    const int smem_bytes = SM_FLOATS * (int)sizeof(float);   // ~76.5 KB
    static bool attr_set = false;
    if (!attr_set) {
        cudaFuncSetAttribute(fused_dist_topk,
                             cudaFuncAttributeMaxDynamicSharedMemorySize, smem_bytes);
        attr_set = true;
    }

    sqnorm_kernel<<<(N + 255) / 256, 256>>>(x);
    fused_dist_topk<<<N / BR, 256, smem_bytes>>>(x);
    refine_kernel<<<N / 4, 128>>>(x);
    relpos_kernel<<<(N * C) / 256, 256>>>(x, tab);
    final_kernel<<<N / 16, 256>>>(W, b, out);
}

// round 6
// speedup vs baseline: 3.2314x; 3.2314x over previous
#include <cuda_runtime.h>
#include <cstdint>
#include <cstddef>

#define N      16384
#define C      128
#define KNN    9
#define KCAND  16
#define COUT   256
#define STRIP  1024            // 1024*16384*4 = 64 MB -> resident in 126 MB L2
#define NSTRIP (N / STRIP)

// Scratch (static __device__ arrays per harness rules; no cudaMalloc anywhere)
__device__ float g_sq[N];
__device__ float g_dist[(size_t)STRIP * N];   // 64 MB strip, L2-resident
__device__ int   g_cand[N * KCAND];
__device__ int   g_nbr[N * KNN];
__device__ float g_x2[(size_t)N * C];

// ---------------------------------------------------------------------------
// 1) squared norms -- replicate an LLVM/XLA vectorized reduce:
//    VF=4, IC=2 -> 8 stride-8 fmaf partial sums, lane-wise combine of the two
//    interleaved vectors, then horizontal tree (l0+l2)+(l1+l3).
// ---------------------------------------------------------------------------
__global__ void sqnorm_kernel(const float* __restrict__ x) {
    int i = blockIdx.x * blockDim.x + threadIdx.x;
    if (i >= N) return;
    const float* r = x + (size_t)i * C;
    float p[8];
#pragma unroll
    for (int l = 0; l < 8; l++) p[l] = 0.f;
#pragma unroll
    for (int k = 0; k < C / 8; k++)
#pragma unroll
        for (int l = 0; l < 8; l++) {
            float v = r[8 * k + l];
            p[l] = fmaf(v, v, p[l]);
        }
    float v0 = p[0] + p[4];
    float v1 = p[1] + p[5];
    float v2 = p[2] + p[6];
    float v3 = p[3] + p[7];
    g_sq[i] = (v0 + v2) + (v1 + v3);
}

// ---------------------------------------------------------------------------
// 2) distance GEMM strip (candidate nomination): ascending-k fp32 FMA chains.
//    dist[i - row0][j] = sq[i] + sq[j] - 2 * x_i . x_j
// ---------------------------------------------------------------------------
__global__ __launch_bounds__(256, 2)
void dist_kernel(const float* __restrict__ x, int row0) {
    __shared__ float As[32][132];   // [k][m] transposed
    __shared__ float Bs[32][132];   // [k][n] transposed

    const int bi  = row0 + blockIdx.y * 128;
    const int bj  = blockIdx.x * 128;
    const int tid = threadIdx.x;
    const int tm  = (tid >> 4) << 3;   // 0..120
    const int tn  = (tid & 15) << 3;   // 0..120

    float acc[8][8];
#pragma unroll
    for (int a = 0; a < 8; a++)
#pragma unroll
        for (int bq = 0; bq < 8; bq++) acc[a][bq] = 0.f;

    for (int k0 = 0; k0 < C; k0 += 32) {
#pragma unroll
        for (int v = 0; v < 4; v++) {
            int idx = tid + v * 256;       // 0..1023
            int r   = idx >> 3;            // 0..127
            int c4  = (idx & 7) << 2;      // 0,4,...,28
            float4 a = *reinterpret_cast<const float4*>(&x[(size_t)(bi + r) * C + k0 + c4]);
            As[c4 + 0][r] = a.x; As[c4 + 1][r] = a.y;
            As[c4 + 2][r] = a.z; As[c4 + 3][r] = a.w;
            float4 bb = *reinterpret_cast<const float4*>(&x[(size_t)(bj + r) * C + k0 + c4]);
            Bs[c4 + 0][r] = bb.x; Bs[c4 + 1][r] = bb.y;
            Bs[c4 + 2][r] = bb.z; Bs[c4 + 3][r] = bb.w;
        }
        __syncthreads();
#pragma unroll
        for (int k = 0; k < 32; k++) {
            float av[8], bv[8];
            *reinterpret_cast<float4*>(&av[0]) = *reinterpret_cast<const float4*>(&As[k][tm]);
            *reinterpret_cast<float4*>(&av[4]) = *reinterpret_cast<const float4*>(&As[k][tm + 4]);
            *reinterpret_cast<float4*>(&bv[0]) = *reinterpret_cast<const float4*>(&Bs[k][tn]);
            *reinterpret_cast<float4*>(&bv[4]) = *reinterpret_cast<const float4*>(&Bs[k][tn + 4]);
#pragma unroll
            for (int a = 0; a < 8; a++)
#pragma unroll
                for (int bq = 0; bq < 8; bq++)
                    acc[a][bq] = fmaf(av[a], bv[bq], acc[a][bq]);
        }
        __syncthreads();
    }

    const float INFV = __int_as_float(0x7f800000);
#pragma unroll
    for (int a = 0; a < 8; a++) {
        int i      = bi + tm + a;
        int lrow   = i - row0;
        float sqi  = g_sq[i];
        float rowv[8];
#pragma unroll
        for (int bq = 0; bq < 8; bq++) {
            int j = bj + tn + bq;
            float dv = (sqi + g_sq[j]) - 2.f * acc[a][bq];
            if (i == j) dv = INFV;
            rowv[bq] = dv;
        }
        float* dst = &g_dist[(size_t)lrow * N + bj + tn];
        *reinterpret_cast<float4*>(dst)     = *reinterpret_cast<float4*>(&rowv[0]);
        *reinterpret_cast<float4*>(dst + 4) = *reinterpret_cast<float4*>(&rowv[4]);
    }
}

// ---------------------------------------------------------------------------
// 3) per-row top-16 smallest CANDIDATES (ties -> lower index).
//    Register-resident unrolled insertion (NO local memory), shared-memory
//    tournament for the block merge. Reads the L2-resident strip.
// ---------------------------------------------------------------------------
__global__ __launch_bounds__(256)
void topk_kernel(int row0) {
    __shared__ float sv[256][KCAND + 1];
    __shared__ int   si[256][KCAND + 1];
    __shared__ float wv[8];
    __shared__ int   wi[8];
    __shared__ int   s_win;

    const int lrow = blockIdx.x;
    const int row  = row0 + lrow;
    const float* d = g_dist + (size_t)lrow * N;
    const int tid  = threadIdx.x;
    const int lane = tid & 31;
    const int warp = tid >> 5;
    const float INFV = __int_as_float(0x7f800000);

    float v[KCAND];
    int   id[KCAND];
#pragma unroll
    for (int q = 0; q < KCAND; q++) { v[q] = INFV; id[q] = 0x7fffffff; }
    float worst = INFV;

    const float4* d4 = reinterpret_cast<const float4*>(d);
#pragma unroll 4
    for (int it = 0; it < N / (256 * 4); it++) {
        float4 q4 = d4[it * 256 + tid];
        int jb = (it * 256 + tid) * 4;
        float cand[4] = {q4.x, q4.y, q4.z, q4.w};
#pragma unroll
        for (int e = 0; e < 4; e++) {
            float dv = cand[e];
            if (dv < worst) {          // rare after warmup; guard is a register cmp
                int jj = jb + e;
#pragma unroll
                for (int q = 0; q < KCAND; q++) {   // unrolled compare-swap chain
                    bool sw = dv < v[q];
                    float tv = sw ? v[q] : dv;  v[q]  = sw ? dv : v[q];  dv = tv;
                    int   ti = sw ? id[q] : jj; id[q] = sw ? jj : id[q]; jj = ti;
                }
                worst = v[KCAND - 1];
            }
        }
    }

    // dump sorted per-thread lists to shared
#pragma unroll
    for (int q = 0; q < KCAND; q++) { sv[tid][q] = v[q]; si[tid][q] = id[q]; }
    __syncthreads();

    int p = 0;   // head pointer into this thread's shared list
    for (int round = 0; round < KCAND; round++) {
        float mv = (p < KCAND) ? sv[tid][p] : INFV;
        int   mi = (p < KCAND) ? si[tid][p] : 0x7fffffff;
#pragma unroll
        for (int s = 16; s > 0; s >>= 1) {
            float ov = __shfl_xor_sync(0xffffffffu, mv, s);
            int   oi = __shfl_xor_sync(0xffffffffu, mi, s);
            if (ov < mv || (ov == mv && oi < mi)) { mv = ov; mi = oi; }
        }
        if (lane == 0) { wv[warp] = mv; wi[warp] = mi; }
        __syncthreads();
        if (tid == 0) {
            float bv = wv[0]; int bi = wi[0];
#pragma unroll
            for (int w = 1; w < 8; w++)
                if (wv[w] < bv || (wv[w] == bv && wi[w] < bi)) { bv = wv[w]; bi = wi[w]; }
            s_win = bi;
            g_cand[row * KCAND + round] = bi;
        }
        __syncthreads();
        if (p < KCAND && si[tid][p] == s_win) p++;   // column sets disjoint -> unique
    }
}

// ---------------------------------------------------------------------------
// 3b) authoritative fp32 re-rank of the 16 candidates, replicating the
//     reference arithmetic: dot = single ascending-k fp32 FMA chain,
//     d = (sq_i + sq_j) - 2*dot, tie-break by lower index.
//     One warp per row; lane t owns candidate t.
// ---------------------------------------------------------------------------
__global__ __launch_bounds__(128)
void refine_kernel(const float* __restrict__ x) {
    __shared__ float sxi[4][128];
    const int warp = threadIdx.x >> 5;
    const int lane = threadIdx.x & 31;
    const int row  = blockIdx.x * 4 + warp;

#pragma unroll
    for (int q = 0; q < 4; q++)
        sxi[warp][lane + 32 * q] = x[(size_t)row * C + lane + 32 * q];
    __syncwarp();

    float d = __int_as_float(0x7f800000);
    int   j = 0x7fffffff;
    if (lane < KCAND) {
        j = g_cand[row * KCAND + lane];
        const float* xj = x + (size_t)j * C;
        float acc = 0.f;
#pragma unroll
        for (int k = 0; k < C; k += 4) {
            float4 v = *reinterpret_cast<const float4*>(xj + k);
            acc = fmaf(sxi[warp][k + 0], v.x, acc);
            acc = fmaf(sxi[warp][k + 1], v.y, acc);
            acc = fmaf(sxi[warp][k + 2], v.z, acc);
            acc = fmaf(sxi[warp][k + 3], v.w, acc);
        }
        d = (g_sq[row] + g_sq[j]) - 2.f * acc;
    }

    // lane 0 gathers, sorts by (d, index) with a static bubble network
    float dv[KCAND];
    int   di[KCAND];
#pragma unroll
    for (int t = 0; t < KCAND; t++) {
        dv[t] = __shfl_sync(0xffffffffu, d, t);
        di[t] = __shfl_sync(0xffffffffu, j, t);
    }
    if (lane == 0) {
#pragma unroll
        for (int a = 0; a < KCAND - 1; a++)
#pragma unroll
            for (int bq = 0; bq < KCAND - 1; bq++) {
                bool sw = dv[bq] > dv[bq + 1] ||
                          (dv[bq] == dv[bq + 1] && di[bq] > di[bq + 1]);
                float tv = sw ? dv[bq + 1] : dv[bq];
                dv[bq + 1] = sw ? dv[bq] : dv[bq + 1]; dv[bq] = tv;
                int ti = sw ? di[bq + 1] : di[bq];
                di[bq + 1] = sw ? di[bq] : di[bq + 1]; di[bq] = ti;
            }
#pragma unroll
        for (int t = 0; t < KNN; t++) g_nbr[row * KNN + t] = di[t];
    }
}

// ---------------------------------------------------------------------------
// 4) x2 = x + rel_pos_table[rel], rel[i] = i/128 - i%128 + 127
// ---------------------------------------------------------------------------
__global__ void relpos_kernel(const float* __restrict__ x, const float* __restrict__ tab) {
    int idx = blockIdx.x * blockDim.x + threadIdx.x;   // over N*C
    int i   = idx >> 7;
    int c   = idx & 127;
    int rel = (i >> 7) - (i & 127) + (C - 1);
    g_x2[idx] = x[idx] + tab[(size_t)rel * C + c];
}

// ---------------------------------------------------------------------------
// 5) gather + max-relative + concat-GEMM (+ bias at the end). 16 rows/block.
// ---------------------------------------------------------------------------
__global__ __launch_bounds__(256)
void final_kernel(const float* __restrict__ W, const float* __restrict__ b,
                  float* __restrict__ out) {
    __shared__ float feat[16][260];   // [x2 | m], padded row
    const int r0   = blockIdx.x * 16;
    const int tid  = threadIdx.x;
    const int half = tid >> 7;
    const int c    = tid & 127;
    const float NEGINF = __int_as_float(0xff800000);

#pragma unroll
    for (int rr = 0; rr < 16; rr += 2) {
        int r = rr + half;
        int i = r0 + r;
        float xi = g_x2[(size_t)i * C + c];
        float m  = NEGINF;
#pragma unroll
        for (int k = 0; k < KNN; k++) {
            int j = g_nbr[i * KNN + k];
            m = fmaxf(m, g_x2[(size_t)j * C + c] - xi);
        }
        feat[r][c]     = xi;
        feat[r][C + c] = m;
    }
    __syncthreads();

    const int o = tid;   // output column 0..255
    float acc[16];
#pragma unroll
    for (int r = 0; r < 16; r++) acc[r] = 0.f;

    for (int f = 0; f < 2 * C; f += 4) {
        float w0 = W[(size_t)(f + 0) * COUT + o];
        float w1 = W[(size_t)(f + 1) * COUT + o];
        float w2 = W[(size_t)(f + 2) * COUT + o];
        float w3 = W[(size_t)(f + 3) * COUT + o];
#pragma unroll
        for (int r = 0; r < 16; r++) {
            float4 fv = *reinterpret_cast<const float4*>(&feat[r][f]);
            acc[r] = fmaf(fv.x, w0, acc[r]);
            acc[r] = fmaf(fv.y, w1, acc[r]);
            acc[r] = fmaf(fv.z, w2, acc[r]);
            acc[r] = fmaf(fv.w, w3, acc[r]);
        }
    }
    float bias = b[o];
#pragma unroll
    for (int r = 0; r < 16; r++)
        out[(size_t)(r0 + r) * COUT + o] = acc[r] + bias;
}

// ---------------------------------------------------------------------------
extern "C" void kernel_launch(void* const* d_in, const int* in_sizes, int n_in,
                              void* d_out, int out_size) {
    const float* x   = (const float*)d_in[0];
    const float* tab = (const float*)d_in[1];
    const float* W   = (const float*)d_in[2];
    const float* b   = (const float*)d_in[3];
    float* out = (float*)d_out;
    (void)in_sizes; (void)n_in; (void)out_size;

    sqnorm_kernel<<<(N + 255) / 256, 256>>>(x);
    for (int s = 0; s < NSTRIP; s++) {
        dist_kernel<<<dim3(N / 128, STRIP / 128), 256>>>(x, s * STRIP);
        topk_kernel<<<STRIP, 256>>>(s * STRIP);
    }
    refine_kernel<<<N / 4, 128>>>(x);
    relpos_kernel<<<(N * C) / 256, 256>>>(x, tab);
    final_kernel<<<N / 16, 256>>>(W, b, out);
}

// round 7
// speedup vs baseline: 3.7024x; 1.1457x over previous
#include <cuda_runtime.h>
#include <cstdint>
#include <cstddef>

#define N      16384
#define C      128
#define KNN    9
#define KCAND  16
#define COUT   256
#define STRIP  1024            // 64 MB strip -> L2-resident
#define NSTRIP (N / STRIP)
#define BUFCAP 1024

// Scratch (static __device__ arrays per harness rules; no cudaMalloc anywhere)
__device__ float g_sq[N];
__device__ float g_dist[(size_t)STRIP * N];   // 64 MB strip, L2-resident
__device__ int   g_cand[N * KCAND];
__device__ int   g_nbr[N * KNN];
__device__ float g_x2[(size_t)N * C];

// ---------------------------------------------------------------------------
// 1) squared norms -- replicate an LLVM/XLA vectorized reduce:
//    VF=4, IC=2 -> 8 stride-8 fmaf partial sums, lane-wise combine of the two
//    interleaved vectors, then horizontal tree (l0+l2)+(l1+l3).
// ---------------------------------------------------------------------------
__global__ void sqnorm_kernel(const float* __restrict__ x) {
    int i = blockIdx.x * blockDim.x + threadIdx.x;
    if (i >= N) return;
    const float* r = x + (size_t)i * C;
    float p[8];
#pragma unroll
    for (int l = 0; l < 8; l++) p[l] = 0.f;
#pragma unroll
    for (int k = 0; k < C / 8; k++)
#pragma unroll
        for (int l = 0; l < 8; l++) {
            float v = r[8 * k + l];
            p[l] = fmaf(v, v, p[l]);
        }
    float v0 = p[0] + p[4];
    float v1 = p[1] + p[5];
    float v2 = p[2] + p[6];
    float v3 = p[3] + p[7];
    g_sq[i] = (v0 + v2) + (v1 + v3);
}

// ---------------------------------------------------------------------------
// 2) distance GEMM strip (candidate nomination): ascending-k fp32 FMA chains.
//    dist[i - row0][j] = sq[i] + sq[j] - 2 * x_i . x_j
// ---------------------------------------------------------------------------
__global__ __launch_bounds__(256, 2)
void dist_kernel(const float* __restrict__ x, int row0) {
    __shared__ float As[32][132];   // [k][m] transposed
    __shared__ float Bs[32][132];   // [k][n] transposed

    const int bi  = row0 + blockIdx.y * 128;
    const int bj  = blockIdx.x * 128;
    const int tid = threadIdx.x;
    const int tm  = (tid >> 4) << 3;   // 0..120
    const int tn  = (tid & 15) << 3;   // 0..120

    float acc[8][8];
#pragma unroll
    for (int a = 0; a < 8; a++)
#pragma unroll
        for (int bq = 0; bq < 8; bq++) acc[a][bq] = 0.f;

    for (int k0 = 0; k0 < C; k0 += 32) {
#pragma unroll
        for (int v = 0; v < 4; v++) {
            int idx = tid + v * 256;       // 0..1023
            int r   = idx >> 3;            // 0..127
            int c4  = (idx & 7) << 2;      // 0,4,...,28
            float4 a = *reinterpret_cast<const float4*>(&x[(size_t)(bi + r) * C + k0 + c4]);
            As[c4 + 0][r] = a.x; As[c4 + 1][r] = a.y;
            As[c4 + 2][r] = a.z; As[c4 + 3][r] = a.w;
            float4 bb = *reinterpret_cast<const float4*>(&x[(size_t)(bj + r) * C + k0 + c4]);
            Bs[c4 + 0][r] = bb.x; Bs[c4 + 1][r] = bb.y;
            Bs[c4 + 2][r] = bb.z; Bs[c4 + 3][r] = bb.w;
        }
        __syncthreads();
#pragma unroll
        for (int k = 0; k < 32; k++) {
            float av[8], bv[8];
            *reinterpret_cast<float4*>(&av[0]) = *reinterpret_cast<const float4*>(&As[k][tm]);
            *reinterpret_cast<float4*>(&av[4]) = *reinterpret_cast<const float4*>(&As[k][tm + 4]);
            *reinterpret_cast<float4*>(&bv[0]) = *reinterpret_cast<const float4*>(&Bs[k][tn]);
            *reinterpret_cast<float4*>(&bv[4]) = *reinterpret_cast<const float4*>(&Bs[k][tn + 4]);
#pragma unroll
            for (int a = 0; a < 8; a++)
#pragma unroll
                for (int bq = 0; bq < 8; bq++)
                    acc[a][bq] = fmaf(av[a], bv[bq], acc[a][bq]);
        }
        __syncthreads();
    }

    const float INFV = __int_as_float(0x7f800000);
#pragma unroll
    for (int a = 0; a < 8; a++) {
        int i      = bi + tm + a;
        int lrow   = i - row0;
        float sqi  = g_sq[i];
        float rowv[8];
#pragma unroll
        for (int bq = 0; bq < 8; bq++) {
            int j = bj + tn + bq;
            float dv = (sqi + g_sq[j]) - 2.f * acc[a][bq];
            if (i == j) dv = INFV;
            rowv[bq] = dv;
        }
        float* dst = &g_dist[(size_t)lrow * N + bj + tn];
        *reinterpret_cast<float4*>(dst)     = *reinterpret_cast<float4*>(&rowv[0]);
        *reinterpret_cast<float4*>(dst + 4) = *reinterpret_cast<float4*>(&rowv[4]);
    }
}

// ---------------------------------------------------------------------------
// 3) per-row top-16 via deterministic threshold two-sweep.
//    Sweep 1: per-thread min of 64 elems -> tau = 16th smallest of the 256
//    thread-minima (each is a distinct element => >=16 elements <= tau).
//    Sweep 2: compact all elements <= tau, then rank-select by (val, idx).
//    Result: exact top-16 by (value, index) -- identical to prior rounds.
// ---------------------------------------------------------------------------
__global__ __launch_bounds__(256)
void topk_kernel(int row0) {
    __shared__ float smin[256];
    __shared__ int   sidx[256];
    __shared__ float s_tau;
    __shared__ int   s_cnt;
    __shared__ float bval[BUFCAP];
    __shared__ int   bidx[BUFCAP];

    const int lrow = blockIdx.x;
    const int row  = row0 + lrow;
    const float* d = g_dist + (size_t)lrow * N;
    const int tid  = threadIdx.x;
    const float INFV = __int_as_float(0x7f800000);

    // sweep 1: per-thread min (strict <, ascending index => lowest-index win)
    const float4* d4 = reinterpret_cast<const float4*>(d);
    float mv = INFV;
    int   mi = 0x7fffffff;
#pragma unroll 4
    for (int it = 0; it < N / (256 * 4); it++) {
        float4 q = d4[it * 256 + tid];
        int jb = (it * 256 + tid) * 4;
        if (q.x < mv) { mv = q.x; mi = jb; }
        if (q.y < mv) { mv = q.y; mi = jb + 1; }
        if (q.z < mv) { mv = q.z; mi = jb + 2; }
        if (q.w < mv) { mv = q.w; mi = jb + 3; }
    }
    smin[tid] = mv; sidx[tid] = mi;
    if (tid == 0) s_cnt = 0;
    __syncthreads();

    // tau = value of the rank-15 minimum (total order by (val, idx))
    int rank = 0;
#pragma unroll 8
    for (int t = 0; t < 256; t++) {
        float ov = smin[t];
        rank += (ov < mv) || (ov == mv && sidx[t] < mi);
    }
    if (rank == 15) s_tau = mv;
    __syncthreads();
    const float tau = s_tau;

    // sweep 2: compact all elements <= tau (expected ~20-30)
#pragma unroll 4
    for (int it = 0; it < N / (256 * 4); it++) {
        float4 q = d4[it * 256 + tid];
        int jb = (it * 256 + tid) * 4;
        float vv[4] = {q.x, q.y, q.z, q.w};
#pragma unroll
        for (int e = 0; e < 4; e++) {
            if (vv[e] <= tau) {
                int p = atomicAdd(&s_cnt, 1);
                if (p < BUFCAP) { bval[p] = vv[e]; bidx[p] = jb + e; }
            }
        }
    }
    __syncthreads();
    const int m = (s_cnt < BUFCAP) ? s_cnt : BUFCAP;

    // rank-select: entry e's rank = #{f : (v_f, i_f) < (v_e, i_e)}
    for (int e = tid; e < m; e += 256) {
        float v = bval[e];
        int   j = bidx[e];
        int r = 0;
        for (int t = 0; t < m; t++) {
            float ov = bval[t];
            r += (ov < v) || (ov == v && bidx[t] < j);
        }
        if (r < KCAND) g_cand[row * KCAND + r] = j;
    }
}

// ---------------------------------------------------------------------------
// 3b) authoritative fp32 re-rank of the 16 candidates, replicating the
//     reference arithmetic: dot = single ascending-k fp32 FMA chain,
//     d = (sq_i + sq_j) - 2*dot, tie-break by lower index.
//     One warp per row; lane t owns candidate t.
// ---------------------------------------------------------------------------
__global__ __launch_bounds__(128)
void refine_kernel(const float* __restrict__ x) {
    __shared__ float sxi[4][128];
    const int warp = threadIdx.x >> 5;
    const int lane = threadIdx.x & 31;
    const int row  = blockIdx.x * 4 + warp;

#pragma unroll
    for (int q = 0; q < 4; q++)
        sxi[warp][lane + 32 * q] = x[(size_t)row * C + lane + 32 * q];
    __syncwarp();

    float d = __int_as_float(0x7f800000);
    int   j = 0x7fffffff;
    if (lane < KCAND) {
        j = g_cand[row * KCAND + lane];
        const float* xj = x + (size_t)j * C;
        float acc = 0.f;
#pragma unroll
        for (int k = 0; k < C; k += 4) {
            float4 v = *reinterpret_cast<const float4*>(xj + k);
            acc = fmaf(sxi[warp][k + 0], v.x, acc);
            acc = fmaf(sxi[warp][k + 1], v.y, acc);
            acc = fmaf(sxi[warp][k + 2], v.z, acc);
            acc = fmaf(sxi[warp][k + 3], v.w, acc);
        }
        d = (g_sq[row] + g_sq[j]) - 2.f * acc;
    }

    // lane 0 gathers, sorts by (d, index) with a static bubble network
    float dv[KCAND];
    int   di[KCAND];
#pragma unroll
    for (int t = 0; t < KCAND; t++) {
        dv[t] = __shfl_sync(0xffffffffu, d, t);
        di[t] = __shfl_sync(0xffffffffu, j, t);
    }
    if (lane == 0) {
#pragma unroll
        for (int a = 0; a < KCAND - 1; a++)
#pragma unroll
            for (int bq = 0; bq < KCAND - 1; bq++) {
                bool sw = dv[bq] > dv[bq + 1] ||
                          (dv[bq] == dv[bq + 1] && di[bq] > di[bq + 1]);
                float tv = sw ? dv[bq + 1] : dv[bq];
                dv[bq + 1] = sw ? dv[bq] : dv[bq + 1]; dv[bq] = tv;
                int ti = sw ? di[bq + 1] : di[bq];
                di[bq + 1] = sw ? di[bq] : di[bq + 1]; di[bq] = ti;
            }
#pragma unroll
        for (int t = 0; t < KNN; t++) g_nbr[row * KNN + t] = di[t];
    }
}

// ---------------------------------------------------------------------------
// 4) x2 = x + rel_pos_table[rel], rel[i] = i/128 - i%128 + 127
// ---------------------------------------------------------------------------
__global__ void relpos_kernel(const float* __restrict__ x, const float* __restrict__ tab) {
    int idx = blockIdx.x * blockDim.x + threadIdx.x;   // over N*C
    int i   = idx >> 7;
    int c   = idx & 127;
    int rel = (i >> 7) - (i & 127) + (C - 1);
    g_x2[idx] = x[idx] + tab[(size_t)rel * C + c];
}

// ---------------------------------------------------------------------------
// 5) gather + max-relative + concat-GEMM (+ bias at the end). 16 rows/block.
// ---------------------------------------------------------------------------
__global__ __launch_bounds__(256)
void final_kernel(const float* __restrict__ W, const float* __restrict__ b,
                  float* __restrict__ out) {
    __shared__ float feat[16][260];   // [x2 | m], padded row
    const int r0   = blockIdx.x * 16;
    const int tid  = threadIdx.x;
    const int half = tid >> 7;
    const int c    = tid & 127;
    const float NEGINF = __int_as_float(0xff800000);

#pragma unroll
    for (int rr = 0; rr < 16; rr += 2) {
        int r = rr + half;
        int i = r0 + r;
        float xi = g_x2[(size_t)i * C + c];
        float m  = NEGINF;
#pragma unroll
        for (int k = 0; k < KNN; k++) {
            int j = g_nbr[i * KNN + k];
            m = fmaxf(m, g_x2[(size_t)j * C + c] - xi);
        }
        feat[r][c]     = xi;
        feat[r][C + c] = m;
    }
    __syncthreads();

    const int o = tid;   // output column 0..255
    float acc[16];
#pragma unroll
    for (int r = 0; r < 16; r++) acc[r] = 0.f;

    for (int f = 0; f < 2 * C; f += 4) {
        float w0 = W[(size_t)(f + 0) * COUT + o];
        float w1 = W[(size_t)(f + 1) * COUT + o];
        float w2 = W[(size_t)(f + 2) * COUT + o];
        float w3 = W[(size_t)(f + 3) * COUT + o];
#pragma unroll
        for (int r = 0; r < 16; r++) {
            float4 fv = *reinterpret_cast<const float4*>(&feat[r][f]);
            acc[r] = fmaf(fv.x, w0, acc[r]);
            acc[r] = fmaf(fv.y, w1, acc[r]);
            acc[r] = fmaf(fv.z, w2, acc[r]);
            acc[r] = fmaf(fv.w, w3, acc[r]);
        }
    }
    float bias = b[o];
#pragma unroll
    for (int r = 0; r < 16; r++)
        out[(size_t)(r0 + r) * COUT + o] = acc[r] + bias;
}

// ---------------------------------------------------------------------------
extern "C" void kernel_launch(void* const* d_in, const int* in_sizes, int n_in,
                              void* d_out, int out_size) {
    const float* x   = (const float*)d_in[0];
    const float* tab = (const float*)d_in[1];
    const float* W   = (const float*)d_in[2];
    const float* b   = (const float*)d_in[3];
    float* out = (float*)d_out;
    (void)in_sizes; (void)n_in; (void)out_size;

    sqnorm_kernel<<<(N + 255) / 256, 256>>>(x);
    for (int s = 0; s < NSTRIP; s++) {
        dist_kernel<<<dim3(N / 128, STRIP / 128), 256>>>(x, s * STRIP);
        topk_kernel<<<STRIP, 256>>>(s * STRIP);
    }
    refine_kernel<<<N / 4, 128>>>(x);
    relpos_kernel<<<(N * C) / 256, 256>>>(x, tab);
    final_kernel<<<N / 16, 256>>>(W, b, out);
}